// round 2
// baseline (speedup 1.0000x reference)
#include <cuda_runtime.h>
#include <cuda_bf16.h>
#include <cstdint>

#define NPROTO 64
#define PDIM   512
#define NFEAT  200000
#define EPSN   1e-8f
#define NACC   148          // accumulation CTAs (== #partial slices)

// ---------------- device scratch (static; no allocation) ----------------
// Prototypes normalized, bf16, pre-permuted for mma B-fragments:
// g_PbP[(proto*32 + kstep)*4 + q] = { bf16x2(P[proto][16k+2q], +1), bf16x2(P[proto][16k+8+2q], +1) }
__device__ uint2         g_PbP[NPROTO * 32 * 4];
__device__ __align__(8) unsigned char g_assign[NFEAT];
__device__ float         g_Partial[NACC * NPROTO * PDIM];   // per-CTA segment sums (~19.4 MB)
__device__ int           g_CntPartial[NACC * NPROTO];

// ---------------- kernel 1: normalize prototypes -> permuted bf16 ----------------
__global__ void prep_kernel(const float* __restrict__ P) {
    int k = blockIdx.x;          // 64 blocks
    int t = threadIdx.x;         // 128 threads
    const float* row = P + k * PDIM;

    float ss = 0.f;
    #pragma unroll
    for (int i = 0; i < 4; ++i) { float v = row[t + 128 * i]; ss += v * v; }
    __shared__ float red[4];
    #pragma unroll
    for (int o = 16; o > 0; o >>= 1) ss += __shfl_xor_sync(0xffffffffu, ss, o);
    if ((t & 31) == 0) red[t >> 5] = ss;
    __syncthreads();
    float norm = sqrtf(red[0] + red[1] + red[2] + red[3]);
    float inv = 1.f / fmaxf(norm, EPSN);

    // thread t handles (kstep = t/4, q = t%4): bf16x2 pairs i0 = ks*8+q and i0+4
    int ks = t >> 2, q = t & 3;
    int i0 = ks * 8 + q;
    float2 fa = make_float2(row[2 * i0] * inv,       row[2 * i0 + 1] * inv);
    float2 fb = make_float2(row[2 * (i0 + 4)] * inv, row[2 * (i0 + 4) + 1] * inv);
    __nv_bfloat162 ha = __float22bfloat162_rn(fa);
    __nv_bfloat162 hb = __float22bfloat162_rn(fb);
    uint2 u;
    u.x = *reinterpret_cast<uint32_t*>(&ha);
    u.y = *reinterpret_cast<uint32_t*>(&hb);
    g_PbP[(k * 32 + ks) * 4 + q] = u;
}

// ---------------- kernel 2: sims GEMM (bf16 mma.sync) + argmax -> assignments ----------------
// One warp computes a 32-row x 64-proto tile: 2 subtiles (m16) x 8 nblk (n8) x 32 ksteps (k16).
__global__ __launch_bounds__(256) void assign_kernel(const float* __restrict__ F) {
    int gw   = (blockIdx.x * blockDim.x + threadIdx.x) >> 5;
    int lane = threadIdx.x & 31;
    const int NTILES = NFEAT / 32;           // 6250
    if (gw >= NTILES) return;
    int rbase = gw * 32;
    int q  = lane & 3;      // k-pair selector within fragment
    int rg = lane >> 2;     // row-in-subtile / proto-in-nblk selector

    float acc[2][8][4];
    #pragma unroll
    for (int s = 0; s < 2; ++s)
        #pragma unroll
        for (int n = 0; n < 8; ++n)
            #pragma unroll
            for (int j = 0; j < 4; ++j) acc[s][n][j] = 0.f;

    const float2* F2 = reinterpret_cast<const float2*>(F);

    for (int ks = 0; ks < 32; ++ks) {
        int ko = ks * 8 + q;                       // float2 index within row
        // B fragments: one LDG.64 per nblk, reused by both subtiles
        uint32_t b0[8], b1[8];
        #pragma unroll
        for (int nb = 0; nb < 8; ++nb) {
            int proto = nb * 8 + rg;
            uint2 bb = g_PbP[(proto * 32 + ks) * 4 + q];
            b0[nb] = bb.x; b1[nb] = bb.y;
        }
        #pragma unroll
        for (int s = 0; s < 2; ++s) {
            int rA = rbase + s * 16 + rg;
            size_t bA = (size_t)rA * (PDIM / 2);
            float2 f0 = F2[bA + ko];                       // row rA,   cols 2q..
            float2 f1 = F2[bA + 8 * (PDIM / 2) + ko];      // row rA+8
            float2 f2 = F2[bA + ko + 4];                   // row rA,   cols +8
            float2 f3 = F2[bA + 8 * (PDIM / 2) + ko + 4];  // row rA+8, cols +8
            uint32_t a0, a1, a2, a3;
            { __nv_bfloat162 h = __float22bfloat162_rn(f0); a0 = *reinterpret_cast<uint32_t*>(&h); }
            { __nv_bfloat162 h = __float22bfloat162_rn(f1); a1 = *reinterpret_cast<uint32_t*>(&h); }
            { __nv_bfloat162 h = __float22bfloat162_rn(f2); a2 = *reinterpret_cast<uint32_t*>(&h); }
            { __nv_bfloat162 h = __float22bfloat162_rn(f3); a3 = *reinterpret_cast<uint32_t*>(&h); }
            #pragma unroll
            for (int nb = 0; nb < 8; ++nb) {
                asm volatile(
                    "mma.sync.aligned.m16n8k16.row.col.f32.bf16.bf16.f32 "
                    "{%0,%1,%2,%3}, {%4,%5,%6,%7}, {%8,%9}, {%0,%1,%2,%3};"
                    : "+f"(acc[s][nb][0]), "+f"(acc[s][nb][1]),
                      "+f"(acc[s][nb][2]), "+f"(acc[s][nb][3])
                    : "r"(a0), "r"(a1), "r"(a2), "r"(a3), "r"(b0[nb]), "r"(b1[nb]));
            }
        }
    }

    // argmax epilogue: each lane holds protos {nb*8 + 2q, +1} for rows rg (d0,d1) and rg+8 (d2,d3)
    #pragma unroll
    for (int s = 0; s < 2; ++s) {
        #pragma unroll
        for (int half = 0; half < 2; ++half) {
            float bv = -3.0e38f; int bi = 0;
            #pragma unroll
            for (int nb = 0; nb < 8; ++nb) {
                #pragma unroll
                for (int j = 0; j < 2; ++j) {
                    float v = acc[s][nb][half * 2 + j];
                    int p = nb * 8 + 2 * q + j;
                    if (v > bv) { bv = v; bi = p; }
                }
            }
            #pragma unroll
            for (int off = 1; off <= 2; off <<= 1) {
                float ov = __shfl_xor_sync(0xffffffffu, bv, off);
                int   oi = __shfl_xor_sync(0xffffffffu, bi, off);
                if (ov > bv || (ov == bv && oi < bi)) { bv = ov; bi = oi; }
            }
            if (q == 0) {
                int row = rbase + s * 16 + half * 8 + rg;
                g_assign[row] = (unsigned char)bi;
            }
        }
    }
}

// ---------------- kernel 3: segment-sum into smem, per-CTA partials ----------------
__global__ __launch_bounds__(512) void accum_kernel(const float* __restrict__ F) {
    extern __shared__ float acc[];          // [64][512] fp32 = 128 KB
    int t = threadIdx.x;                    // thread t owns column t (conflict-free)
    #pragma unroll
    for (int i = 0; i < NPROTO; ++i) acc[i * PDIM + t] = 0.f;
    __syncthreads();

    const int RPC = 1352;                   // 148 * 1352 >= 200000, multiple of 8
    int base = blockIdx.x * RPC;
    int end  = min(base + RPC, NFEAT);
    int cnt  = 0;

    float v[2][8];
    unsigned long long asg[2];
    // prologue: load batch 0
    asg[0] = *reinterpret_cast<const unsigned long long*>(g_assign + base);
    #pragma unroll
    for (int j = 0; j < 8; ++j) v[0][j] = F[(size_t)(base + j) * PDIM + t];

    int buf = 0;
    for (int r = base; r < end; r += 8) {
        int nr = r + 8;
        if (nr < end) {
            asg[buf ^ 1] = *reinterpret_cast<const unsigned long long*>(g_assign + nr);
            #pragma unroll
            for (int j = 0; j < 8; ++j) v[buf ^ 1][j] = F[(size_t)(nr + j) * PDIM + t];
        }
        unsigned long long a8 = asg[buf];
        #pragma unroll
        for (int j = 0; j < 8; ++j) {
            int a = (int)((a8 >> (8 * j)) & 0xFFull);
            acc[a * PDIM + t] += v[buf][j];
        }
        if (t < NPROTO) {
            #pragma unroll
            for (int j = 0; j < 8; ++j)
                cnt += (((a8 >> (8 * j)) & 0xFFull) == (unsigned long long)t);
        }
        buf ^= 1;
    }
    __syncthreads();

    // deterministic flush: plain stores of this CTA's partial slice
    float* part = g_Partial + (size_t)blockIdx.x * (NPROTO * PDIM);
    #pragma unroll 4
    for (int k = 0; k < NPROTO; ++k) part[k * PDIM + t] = acc[k * PDIM + t];
    if (t < NPROTO) g_CntPartial[blockIdx.x * NPROTO + t] = cnt;
}

// ---------------- kernel 4: reduce partials + EMA update ----------------
__global__ void finalize_kernel(const float* __restrict__ P, float* __restrict__ out) {
    int k = blockIdx.x;      // 64
    int t = threadIdx.x;     // 512
    float s = 0.f;
    int   c = 0;
    for (int b = 0; b < NACC; ++b) {
        s += g_Partial[(size_t)b * (NPROTO * PDIM) + k * PDIM + t];
        c += g_CntPartial[b * NPROTO + k];   // broadcast load, same addr all threads
    }
    float cf = (float)c;
    float p = P[k * PDIM + t];
    float mean = s / fmaxf(cf, 1.f);
    out[k * PDIM + t] = (c > 0) ? (0.9f * p + 0.1f * mean) : p;
}

// ---------------- launch ----------------
extern "C" void kernel_launch(void* const* d_in, const int* in_sizes, int n_in,
                              void* d_out, int out_size) {
    const float* F = (const float*)d_in[0];
    const float* P = (const float*)d_in[1];
    if (in_sizes[0] == NPROTO * PDIM) {     // robust to input order
        F = (const float*)d_in[1];
        P = (const float*)d_in[0];
    }

    prep_kernel<<<NPROTO, 128>>>(P);

    // 6250 warp-tiles, 8 warps/CTA -> 782 CTAs
    assign_kernel<<<(NFEAT / 32 + 7) / 8, 256>>>(F);

    cudaFuncSetAttribute(accum_kernel, cudaFuncAttributeMaxDynamicSharedMemorySize,
                         NPROTO * PDIM * (int)sizeof(float));
    accum_kernel<<<NACC, 512, NPROTO * PDIM * sizeof(float)>>>(F);

    finalize_kernel<<<NPROTO, 512>>>(P, (float*)d_out);
}